// round 15
// baseline (speedup 1.0000x reference)
#include <cuda_runtime.h>
#include <cuda_fp16.h>
#include <cstdint>
#include <cstddef>

#define N_USERS 50000
#define N_ENT   100000
#define N_TOT   150000
#define D       64
#define NTILES  ((N_TOT + 127) / 128)   // 1172
#define EDGE_BLOCKS 888                  // 6 blocks/SM x 148 SM: one resident wave

// ---------------------------------------------------------------------------
// Scratch: y = x @ W in fp16, softmax denominator, grid-barrier counter.
// ---------------------------------------------------------------------------
__device__ __align__(256) __half g_yh[(size_t)N_TOT * D];
__device__ float g_Z;
__device__ int g_done = 0;

__device__ __forceinline__ uint32_t smem_u32(const void* p) {
    return (uint32_t)__cvta_generic_to_shared(p);
}

// ---------------------------------------------------------------------------
// build: y = x @ W via HMMA m16n8k16, persistent tiles, B fragments in regs.
// Also resets g_Z and g_done (stream-ordered before the fused edge kernel).
// ---------------------------------------------------------------------------
__global__ void __launch_bounds__(256) build_y_kernel(
    const int* __restrict__ uidx, const int* __restrict__ iidx,
    const float* __restrict__ ut, const float* __restrict__ et,
    const float* __restrict__ W)
{
    __shared__ __align__(16) __half Wh[64][72];
    __shared__ __align__(16) __half Xh[128][72];

    if (blockIdx.x == 0 && threadIdx.x == 0) { g_Z = 0.0f; g_done = 0; }

    const int tid  = threadIdx.x;
    const int warp = tid >> 5;
    const int lane = tid & 31;

    // W -> fp16 smem (once per block)
    {
        const int k  = tid >> 2;
        const int n0 = (tid & 3) * 16;
        #pragma unroll
        for (int i = 0; i < 16; i += 4) {
            float4 v = *(const float4*)(W + k * 64 + n0 + i);
            __half2 h0 = __floats2half2_rn(v.x, v.y);
            __half2 h1 = __floats2half2_rn(v.z, v.w);
            *(uint2*)&Wh[k][n0 + i] = make_uint2(*(unsigned*)&h0, *(unsigned*)&h1);
        }
    }
    __syncthreads();

    // hoist all B fragments to registers (once per warp)
    uint32_t bf[4][8][2];
    #pragma unroll
    for (int kk = 0; kk < 4; kk++) {
        #pragma unroll
        for (int j = 0; j < 8; j++) {
            uint32_t addr = smem_u32(&Wh[kk * 16 + (lane & 15)][j * 8]);
            asm volatile("ldmatrix.sync.aligned.m8n8.x2.trans.shared.b16 {%0,%1}, [%2];"
                         : "=r"(bf[kk][j][0]), "=r"(bf[kk][j][1]) : "r"(addr));
        }
    }

    const int grp  = lane >> 3;
    const int lrow = lane & 7;
    const int trow = lane >> 2;
    const int tcol = (lane & 3) * 2;

    for (int tile = blockIdx.x; tile < NTILES; tile += gridDim.x) {
        const int row0g = tile * 128;

        __syncthreads();

        {
            const int lr = tid >> 1;
            const int hx = (tid & 1) * 32;
            const int r  = row0g + lr;
            if (r < N_TOT) {
                const float* xrow;
                if (r < N_USERS) xrow = ut + (size_t)__ldg(uidx + r) * D;
                else             xrow = et + (size_t)__ldg(iidx + (r - N_USERS)) * D;
                #pragma unroll
                for (int i = 0; i < 8; i++) {
                    float4 v = *(const float4*)(xrow + hx + i * 4);
                    __half2 h0 = __floats2half2_rn(v.x, v.y);
                    __half2 h1 = __floats2half2_rn(v.z, v.w);
                    *(uint2*)&Xh[lr][hx + i * 4] =
                        make_uint2(*(unsigned*)&h0, *(unsigned*)&h1);
                }
            } else {
                #pragma unroll
                for (int i = 0; i < 8; i++)
                    *(uint2*)&Xh[lr][hx + i * 4] = make_uint2(0u, 0u);
            }
        }
        __syncthreads();

        const int row0 = warp * 16;

        float c[8][4];
        #pragma unroll
        for (int j = 0; j < 8; j++)
            #pragma unroll
            for (int q = 0; q < 4; q++) c[j][q] = 0.f;

        #pragma unroll
        for (int kk = 0; kk < 4; kk++) {
            const int arow = row0 + lrow + ((grp & 1) ? 8 : 0);
            const int acol = kk * 16 + ((grp & 2) ? 8 : 0);
            uint32_t a0, a1, a2, a3;
            {
                uint32_t addr = smem_u32(&Xh[arow][acol]);
                asm volatile("ldmatrix.sync.aligned.m8n8.x4.shared.b16 {%0,%1,%2,%3}, [%4];"
                             : "=r"(a0), "=r"(a1), "=r"(a2), "=r"(a3) : "r"(addr));
            }
            #pragma unroll
            for (int j = 0; j < 8; j++) {
                asm volatile(
                    "mma.sync.aligned.m16n8k16.row.col.f32.f16.f16.f32 "
                    "{%0,%1,%2,%3}, {%4,%5,%6,%7}, {%8,%9}, {%0,%1,%2,%3};"
                    : "+f"(c[j][0]), "+f"(c[j][1]), "+f"(c[j][2]), "+f"(c[j][3])
                    : "r"(a0), "r"(a1), "r"(a2), "r"(a3),
                      "r"(bf[kk][j][0]), "r"(bf[kk][j][1]));
            }
        }

        const int gr0 = row0g + row0 + trow;
        const int gr1 = gr0 + 8;
        #pragma unroll
        for (int j = 0; j < 8; j++) {
            const int col = j * 8 + tcol;
            if (gr0 < N_TOT) {
                __half2 h = __floats2half2_rn(c[j][0], c[j][1]);
                *(__half2*)(g_yh + (size_t)gr0 * D + col) = h;
            }
            if (gr1 < N_TOT) {
                __half2 h = __floats2half2_rn(c[j][2], c[j][3]);
                *(__half2*)(g_yh + (size_t)gr1 * D + col) = h;
            }
        }
    }
}

// ---------------------------------------------------------------------------
// Fused edge + finalize: R9 edge shape; then a single-wave grid barrier
// (guaranteed: __launch_bounds__(256,6) x 888 blocks = exactly resident);
// then normalize out while it is still L2-resident.
// ---------------------------------------------------------------------------
__global__ void __launch_bounds__(256, 6) edge_finalize_kernel(
    const int* __restrict__ ei, int E, float* __restrict__ out, int n)
{
    const int tid  = threadIdx.x;
    const int lane = tid & 31;
    const int li   = lane & 15;
    const unsigned mask = 0xFFFFu << ((lane >> 4) * 16);
    const int gid  = (blockIdx.x * blockDim.x + tid) >> 4;
    const int ng   = (gridDim.x * blockDim.x) >> 4;

    float zloc = 0.0f;

    for (int e = gid; e < E; e += ng) {
        const int src = __ldg(ei + e);
        const int dst = __ldg(ei + E + e);

        uint2 us = __ldg((const uint2*)(g_yh + (size_t)src * D) + li);
        uint2 ud = __ldg((const uint2*)(g_yh + (size_t)dst * D) + li);
        float2 s0 = __half22float2(*(__half2*)&us.x);
        float2 s1 = __half22float2(*(__half2*)&us.y);
        float2 d0 = __half22float2(*(__half2*)&ud.x);
        float2 d1 = __half22float2(*(__half2*)&ud.y);

        float t = s0.x * d0.x + s0.y * d0.y + s1.x * d1.x + s1.y * d1.y;
        t += __shfl_xor_sync(mask, t, 8);
        t += __shfl_xor_sync(mask, t, 4);
        t += __shfl_xor_sync(mask, t, 2);
        t += __shfl_xor_sync(mask, t, 1);

        const float p = __expf(t >= 0.f ? t : 0.2f * t);   // leaky_relu(0.2)
        if (li == 0) zloc += p;

        float* dp = out + (size_t)dst * D + li * 4;
        asm volatile("red.global.add.v4.f32 [%0], {%1,%2,%3,%4};"
                     :: "l"(dp), "f"(p * s0.x), "f"(p * s0.y),
                        "f"(p * s1.x), "f"(p * s1.y)
                     : "memory");
    }

    // block Z reduction -> g_Z
    float z = zloc;
    #pragma unroll
    for (int o = 16; o > 0; o >>= 1) z += __shfl_xor_sync(0xffffffffu, z, o);
    __shared__ float sz[8];
    if (lane == 0) sz[tid >> 5] = z;
    __syncthreads();
    if (tid == 0) {
        float s = 0.f;
        #pragma unroll
        for (int w = 0; w < 8; w++) s += sz[w];
        atomicAdd(&g_Z, s);
    }

    // grid barrier: make this thread's reds visible, then count blocks in
    __threadfence();
    __syncthreads();
    if (tid == 0) {
        atomicAdd(&g_done, 1);
        while (atomicAdd(&g_done, 0) < (int)gridDim.x) { /* spin */ }
        __threadfence();
    }
    __syncthreads();

    // finalize: out = relu(out) / Z (out is L2-warm from the reds)
    const float invZ = 1.0f / *(volatile float*)&g_Z;
    const int n4 = n >> 2;
    float4* o4 = (float4*)out;
    const int st = gridDim.x * blockDim.x;
    for (int i = blockIdx.x * blockDim.x + tid; i < n4; i += st) {
        float4 v = o4[i];
        v.x = v.x > 0.f ? v.x * invZ : 0.f;
        v.y = v.y > 0.f ? v.y * invZ : 0.f;
        v.z = v.z > 0.f ? v.z * invZ : 0.f;
        v.w = v.w > 0.f ? v.w * invZ : 0.f;
        o4[i] = v;
    }
}

// ---------------------------------------------------------------------------
// Launch: memset(out) on side stream ∥ build_y (resets Z/done); join;
// fused edge+finalize (single resident wave).
// ---------------------------------------------------------------------------
extern "C" void kernel_launch(void* const* d_in, const int* in_sizes, int n_in,
                              void* d_out, int out_size)
{
    const int*   uidx = (const int*)d_in[0];
    const int*   iidx = (const int*)d_in[1];
    const int*   ei   = (const int*)d_in[2];
    const float* ut   = (const float*)d_in[5];
    const float* et   = (const float*)d_in[6];
    const float* W    = (const float*)d_in[7];
    float* out = (float*)d_out;
    const int E = in_sizes[2] / 2;

    static cudaStream_t s2 = nullptr;
    static cudaEvent_t ev_fork = nullptr, ev_join = nullptr;
    if (s2 == nullptr) {
        cudaStreamCreateWithFlags(&s2, cudaStreamNonBlocking);
        cudaEventCreateWithFlags(&ev_fork, cudaEventDisableTiming);
        cudaEventCreateWithFlags(&ev_join, cudaEventDisableTiming);
    }

    cudaEventRecord(ev_fork, 0);
    cudaStreamWaitEvent(s2, ev_fork, 0);
    cudaMemsetAsync(out, 0, (size_t)out_size * sizeof(float), s2);
    cudaEventRecord(ev_join, s2);

    build_y_kernel<<<296, 256>>>(uidx, iidx, ut, et, W);

    cudaStreamWaitEvent(0, ev_join, 0);
    edge_finalize_kernel<<<EDGE_BLOCKS, 256>>>(ei, E, out, out_size);
}

// round 16
// speedup vs baseline: 1.0821x; 1.0821x over previous
#include <cuda_runtime.h>
#include <cuda_fp16.h>
#include <cstdint>
#include <cstddef>

#define N_USERS 50000
#define N_ENT   100000
#define N_TOT   150000
#define D       64
#define NTILES  ((N_TOT + 127) / 128)   // 1172

// ---------------------------------------------------------------------------
// Scratch: y = x @ W in fp16 (sole consumer: edge pass), softmax denominator.
// ---------------------------------------------------------------------------
__device__ __align__(256) __half g_yh[(size_t)N_TOT * D];
__device__ float g_Z;

__device__ __forceinline__ uint32_t smem_u32(const void* p) {
    return (uint32_t)__cvta_generic_to_shared(p);
}

// ---------------------------------------------------------------------------
// build: y = x @ W via HMMA m16n8k16, persistent tiles, B fragments hoisted
// to registers. Tile = 128 rows, 256 threads (8 warps x 16 rows).
// ---------------------------------------------------------------------------
__global__ void __launch_bounds__(256) build_y_kernel(
    const int* __restrict__ uidx, const int* __restrict__ iidx,
    const float* __restrict__ ut, const float* __restrict__ et,
    const float* __restrict__ W)
{
    __shared__ __align__(16) __half Wh[64][72];
    __shared__ __align__(16) __half Xh[128][72];

    if (blockIdx.x == 0 && threadIdx.x == 0) g_Z = 0.0f;

    const int tid  = threadIdx.x;
    const int warp = tid >> 5;
    const int lane = tid & 31;

    // W -> fp16 smem (once per block)
    {
        const int k  = tid >> 2;
        const int n0 = (tid & 3) * 16;
        #pragma unroll
        for (int i = 0; i < 16; i += 4) {
            float4 v = *(const float4*)(W + k * 64 + n0 + i);
            __half2 h0 = __floats2half2_rn(v.x, v.y);
            __half2 h1 = __floats2half2_rn(v.z, v.w);
            *(uint2*)&Wh[k][n0 + i] = make_uint2(*(unsigned*)&h0, *(unsigned*)&h1);
        }
    }
    __syncthreads();

    // hoist all B fragments to registers (once per warp)
    uint32_t bf[4][8][2];
    #pragma unroll
    for (int kk = 0; kk < 4; kk++) {
        #pragma unroll
        for (int j = 0; j < 8; j++) {
            uint32_t addr = smem_u32(&Wh[kk * 16 + (lane & 15)][j * 8]);
            asm volatile("ldmatrix.sync.aligned.m8n8.x2.trans.shared.b16 {%0,%1}, [%2];"
                         : "=r"(bf[kk][j][0]), "=r"(bf[kk][j][1]) : "r"(addr));
        }
    }

    const int grp  = lane >> 3;
    const int lrow = lane & 7;
    const int trow = lane >> 2;
    const int tcol = (lane & 3) * 2;

    for (int tile = blockIdx.x; tile < NTILES; tile += gridDim.x) {
        const int row0g = tile * 128;

        __syncthreads();   // previous tile's ldmatrix reads done before restage

        // x gather -> fp16 smem: 2 threads per row, 32 floats each
        {
            const int lr = tid >> 1;
            const int hx = (tid & 1) * 32;
            const int r  = row0g + lr;
            if (r < N_TOT) {
                const float* xrow;
                if (r < N_USERS) xrow = ut + (size_t)__ldg(uidx + r) * D;
                else             xrow = et + (size_t)__ldg(iidx + (r - N_USERS)) * D;
                #pragma unroll
                for (int i = 0; i < 8; i++) {
                    float4 v = *(const float4*)(xrow + hx + i * 4);
                    __half2 h0 = __floats2half2_rn(v.x, v.y);
                    __half2 h1 = __floats2half2_rn(v.z, v.w);
                    *(uint2*)&Xh[lr][hx + i * 4] =
                        make_uint2(*(unsigned*)&h0, *(unsigned*)&h1);
                }
            } else {
                #pragma unroll
                for (int i = 0; i < 8; i++)
                    *(uint2*)&Xh[lr][hx + i * 4] = make_uint2(0u, 0u);
            }
        }
        __syncthreads();

        const int row0 = warp * 16;

        float c[8][4];
        #pragma unroll
        for (int j = 0; j < 8; j++)
            #pragma unroll
            for (int q = 0; q < 4; q++) c[j][q] = 0.f;

        #pragma unroll
        for (int kk = 0; kk < 4; kk++) {
            const int arow = row0 + lrow + ((grp & 1) ? 8 : 0);
            const int acol = kk * 16 + ((grp & 2) ? 8 : 0);
            uint32_t a0, a1, a2, a3;
            {
                uint32_t addr = smem_u32(&Xh[arow][acol]);
                asm volatile("ldmatrix.sync.aligned.m8n8.x4.shared.b16 {%0,%1,%2,%3}, [%4];"
                             : "=r"(a0), "=r"(a1), "=r"(a2), "=r"(a3) : "r"(addr));
            }
            #pragma unroll
            for (int j = 0; j < 8; j++) {
                asm volatile(
                    "mma.sync.aligned.m16n8k16.row.col.f32.f16.f16.f32 "
                    "{%0,%1,%2,%3}, {%4,%5,%6,%7}, {%8,%9}, {%0,%1,%2,%3};"
                    : "+f"(c[j][0]), "+f"(c[j][1]), "+f"(c[j][2]), "+f"(c[j][3])
                    : "r"(a0), "r"(a1), "r"(a2), "r"(a3),
                      "r"(bf[kk][j][0]), "r"(bf[kk][j][1]));
            }
        }

        const int gr0 = row0g + row0 + trow;
        const int gr1 = gr0 + 8;
        #pragma unroll
        for (int j = 0; j < 8; j++) {
            const int col = j * 8 + tcol;
            if (gr0 < N_TOT) {
                __half2 h = __floats2half2_rn(c[j][0], c[j][1]);
                *(__half2*)(g_yh + (size_t)gr0 * D + col) = h;
            }
            if (gr1 < N_TOT) {
                __half2 h = __floats2half2_rn(c[j][2], c[j][3]);
                *(__half2*)(g_yh + (size_t)gr1 * D + col) = h;
            }
        }
    }
}

// ---------------------------------------------------------------------------
// Fused edge pass: exact R9/R14 shape, but __launch_bounds__(256, 8) caps regs
// at 32 -> 8 blocks/SM resident (was 6 @ 40 regs) for better latency cover.
// ---------------------------------------------------------------------------
__global__ void __launch_bounds__(256, 8) edge_kernel(
    const int* __restrict__ ei, int E, float* __restrict__ out)
{
    const int lane = threadIdx.x & 31;
    const int li   = lane & 15;
    const unsigned mask = 0xFFFFu << ((lane >> 4) * 16);
    const int gid  = (blockIdx.x * blockDim.x + threadIdx.x) >> 4;
    const int ng   = (gridDim.x * blockDim.x) >> 4;

    float zloc = 0.0f;

    for (int e = gid; e < E; e += ng) {
        const int src = __ldg(ei + e);
        const int dst = __ldg(ei + E + e);

        uint2 us = __ldg((const uint2*)(g_yh + (size_t)src * D) + li);
        uint2 ud = __ldg((const uint2*)(g_yh + (size_t)dst * D) + li);
        float2 s0 = __half22float2(*(__half2*)&us.x);
        float2 s1 = __half22float2(*(__half2*)&us.y);
        float2 d0 = __half22float2(*(__half2*)&ud.x);
        float2 d1 = __half22float2(*(__half2*)&ud.y);

        float t = s0.x * d0.x + s0.y * d0.y + s1.x * d1.x + s1.y * d1.y;
        t += __shfl_xor_sync(mask, t, 8);
        t += __shfl_xor_sync(mask, t, 4);
        t += __shfl_xor_sync(mask, t, 2);
        t += __shfl_xor_sync(mask, t, 1);

        const float p = __expf(t >= 0.f ? t : 0.2f * t);   // leaky_relu(0.2)
        if (li == 0) zloc += p;

        float* dp = out + (size_t)dst * D + li * 4;
        asm volatile("red.global.add.v4.f32 [%0], {%1,%2,%3,%4};"
                     :: "l"(dp), "f"(p * s0.x), "f"(p * s0.y),
                        "f"(p * s1.x), "f"(p * s1.y)
                     : "memory");
    }

    // block-reduce zloc -> one atomic per block (loop done; full mask safe)
    float z = zloc;
    #pragma unroll
    for (int o = 16; o > 0; o >>= 1) z += __shfl_xor_sync(0xffffffffu, z, o);
    __shared__ float sz[8];
    if (lane == 0) sz[threadIdx.x >> 5] = z;
    __syncthreads();
    if (threadIdx.x == 0) {
        float s = 0.f;
        #pragma unroll
        for (int w = 0; w < 8; w++) s += sz[w];
        atomicAdd(&g_Z, s);
    }
}

// ---------------------------------------------------------------------------
// finalize: out = relu(out) / Z
// ---------------------------------------------------------------------------
__global__ void __launch_bounds__(256) finalize_kernel(float* __restrict__ out, int n)
{
    const float invZ = 1.0f / g_Z;
    const int n4 = n >> 2;
    float4* o4 = (float4*)out;
    const int st = gridDim.x * blockDim.x;
    for (int i = blockIdx.x * blockDim.x + threadIdx.x; i < n4; i += st) {
        float4 v = o4[i];
        v.x = v.x > 0.f ? v.x * invZ : 0.f;
        v.y = v.y > 0.f ? v.y * invZ : 0.f;
        v.z = v.z > 0.f ? v.z * invZ : 0.f;
        v.w = v.w > 0.f ? v.w * invZ : 0.f;
        o4[i] = v;
    }
}

// ---------------------------------------------------------------------------
// Launch: memset(out) on side stream ∥ build_y (also zeroes Z); join; edge;
// finalize.
// ---------------------------------------------------------------------------
extern "C" void kernel_launch(void* const* d_in, const int* in_sizes, int n_in,
                              void* d_out, int out_size)
{
    const int*   uidx = (const int*)d_in[0];
    const int*   iidx = (const int*)d_in[1];
    const int*   ei   = (const int*)d_in[2];
    const float* ut   = (const float*)d_in[5];
    const float* et   = (const float*)d_in[6];
    const float* W    = (const float*)d_in[7];
    float* out = (float*)d_out;
    const int E = in_sizes[2] / 2;

    static cudaStream_t s2 = nullptr;
    static cudaEvent_t ev_fork = nullptr, ev_join = nullptr;
    if (s2 == nullptr) {
        cudaStreamCreateWithFlags(&s2, cudaStreamNonBlocking);
        cudaEventCreateWithFlags(&ev_fork, cudaEventDisableTiming);
        cudaEventCreateWithFlags(&ev_join, cudaEventDisableTiming);
    }

    cudaEventRecord(ev_fork, 0);
    cudaStreamWaitEvent(s2, ev_fork, 0);
    cudaMemsetAsync(out, 0, (size_t)out_size * sizeof(float), s2);
    cudaEventRecord(ev_join, s2);

    build_y_kernel<<<296, 256>>>(uidx, iidx, ut, et, W);

    cudaStreamWaitEvent(0, ev_join, 0);
    edge_kernel<<<1184, 256>>>(ei, E, out);
    finalize_kernel<<<1184, 256>>>(out, out_size);
}

// round 17
// speedup vs baseline: 1.1295x; 1.0437x over previous
#include <cuda_runtime.h>
#include <cuda_fp16.h>
#include <cstdint>
#include <cstddef>

#define N_USERS 50000
#define N_ENT   100000
#define N_TOT   150000
#define D       64
#define NTILES  ((N_TOT + 127) / 128)   // 1172

// ---------------------------------------------------------------------------
// Scratch: y = x @ W in fp16 (sole consumer: edge pass), softmax denominator.
// ---------------------------------------------------------------------------
__device__ __align__(256) __half g_yh[(size_t)N_TOT * D];
__device__ float g_Z;

__device__ __forceinline__ uint32_t smem_u32(const void* p) {
    return (uint32_t)__cvta_generic_to_shared(p);
}

__device__ __forceinline__ uint32_t f2h2(float a, float b) {
    __half2 h = __floats2half2_rn(a, b);
    return *(uint32_t*)&h;
}

// ---------------------------------------------------------------------------
// build: y = x @ W via HMMA m16n8k16. NO X staging: each warp gathers its A
// fragments straight from global (per-lane fragment addressing, 100%-efficient
// 8-sector LDG.64s), B fragments hoisted to registers. No per-tile syncs.
// 256 threads = 8 warps x 16 rows; persistent over tiles.
// ---------------------------------------------------------------------------
__global__ void __launch_bounds__(256) build_y_kernel(
    const int* __restrict__ uidx, const int* __restrict__ iidx,
    const float* __restrict__ ut, const float* __restrict__ et,
    const float* __restrict__ W)
{
    __shared__ __align__(16) __half Wh[64][72];   // 9.2 KB (bf staging only)

    if (blockIdx.x == 0 && threadIdx.x == 0) g_Z = 0.0f;

    const int tid  = threadIdx.x;
    const int warp = tid >> 5;
    const int lane = tid & 31;

    // W -> fp16 smem (once per block)
    {
        const int k  = tid >> 2;
        const int n0 = (tid & 3) * 16;
        #pragma unroll
        for (int i = 0; i < 16; i += 4) {
            float4 v = *(const float4*)(W + k * 64 + n0 + i);
            *(uint2*)&Wh[k][n0 + i] = make_uint2(f2h2(v.x, v.y), f2h2(v.z, v.w));
        }
    }
    __syncthreads();

    // hoist all B fragments to registers (once per warp)
    uint32_t bf[4][8][2];
    #pragma unroll
    for (int kk = 0; kk < 4; kk++) {
        #pragma unroll
        for (int j = 0; j < 8; j++) {
            uint32_t addr = smem_u32(&Wh[kk * 16 + (lane & 15)][j * 8]);
            asm volatile("ldmatrix.sync.aligned.m8n8.x2.trans.shared.b16 {%0,%1}, [%2];"
                         : "=r"(bf[kk][j][0]), "=r"(bf[kk][j][1]) : "r"(addr));
        }
    }

    const int trow = lane >> 2;          // 0..7
    const int tcol = (lane & 3) * 2;

    for (int tile = blockIdx.x; tile < NTILES; tile += gridDim.x) {
        const int rbase = tile * 128 + warp * 16;

        // per-lane row pointer for rows rbase+0..15 (lanes 0-15), then share
        const int rl = rbase + lane;
        const int rc = rl < N_TOT ? rl : N_TOT - 1;
        const float* prow = (rc < N_USERS)
            ? ut + (size_t)__ldg(uidx + rc) * D
            : et + (size_t)__ldg(iidx + (rc - N_USERS)) * D;
        unsigned long long pl = (unsigned long long)prow;
        const float* xlo = (const float*)__shfl_sync(0xffffffffu, pl, trow);
        const float* xhi = (const float*)__shfl_sync(0xffffffffu, pl, trow + 8);

        float c[8][4];
        #pragma unroll
        for (int j = 0; j < 8; j++)
            #pragma unroll
            for (int q = 0; q < 4; q++) c[j][q] = 0.f;

        #pragma unroll
        for (int kk = 0; kk < 4; kk++) {
            const int cc = kk * 16 + tcol;
            float2 f0 = *(const float2*)(xlo + cc);        // A[r][c..c+1]
            float2 f1 = *(const float2*)(xhi + cc);        // A[r+8][c..c+1]
            float2 f2 = *(const float2*)(xlo + cc + 8);    // A[r][c+8..]
            float2 f3 = *(const float2*)(xhi + cc + 8);    // A[r+8][c+8..]
            uint32_t a0 = f2h2(f0.x, f0.y);
            uint32_t a1 = f2h2(f1.x, f1.y);
            uint32_t a2 = f2h2(f2.x, f2.y);
            uint32_t a3 = f2h2(f3.x, f3.y);

            #pragma unroll
            for (int j = 0; j < 8; j++) {
                asm volatile(
                    "mma.sync.aligned.m16n8k16.row.col.f32.f16.f16.f32 "
                    "{%0,%1,%2,%3}, {%4,%5,%6,%7}, {%8,%9}, {%0,%1,%2,%3};"
                    : "+f"(c[j][0]), "+f"(c[j][1]), "+f"(c[j][2]), "+f"(c[j][3])
                    : "r"(a0), "r"(a1), "r"(a2), "r"(a3),
                      "r"(bf[kk][j][0]), "r"(bf[kk][j][1]));
            }
        }

        const int gr0 = rbase + trow;
        const int gr1 = gr0 + 8;
        #pragma unroll
        for (int j = 0; j < 8; j++) {
            const int col = j * 8 + tcol;
            if (gr0 < N_TOT)
                *(__half2*)(g_yh + (size_t)gr0 * D + col) =
                    __floats2half2_rn(c[j][0], c[j][1]);
            if (gr1 < N_TOT)
                *(__half2*)(g_yh + (size_t)gr1 * D + col) =
                    __floats2half2_rn(c[j][2], c[j][3]);
        }
    }
}

// ---------------------------------------------------------------------------
// Fused edge pass: R9/R14 shape (measured best). 16 lanes per edge, fp16
// gathers, 4-shuffle dot, red.global.add.v4 scatter, Z accumulate.
// ---------------------------------------------------------------------------
__global__ void __launch_bounds__(256, 8) edge_kernel(
    const int* __restrict__ ei, int E, float* __restrict__ out)
{
    const int lane = threadIdx.x & 31;
    const int li   = lane & 15;
    const unsigned mask = 0xFFFFu << ((lane >> 4) * 16);
    const int gid  = (blockIdx.x * blockDim.x + threadIdx.x) >> 4;
    const int ng   = (gridDim.x * blockDim.x) >> 4;

    float zloc = 0.0f;

    for (int e = gid; e < E; e += ng) {
        const int src = __ldg(ei + e);
        const int dst = __ldg(ei + E + e);

        uint2 us = __ldg((const uint2*)(g_yh + (size_t)src * D) + li);
        uint2 ud = __ldg((const uint2*)(g_yh + (size_t)dst * D) + li);
        float2 s0 = __half22float2(*(__half2*)&us.x);
        float2 s1 = __half22float2(*(__half2*)&us.y);
        float2 d0 = __half22float2(*(__half2*)&ud.x);
        float2 d1 = __half22float2(*(__half2*)&ud.y);

        float t = s0.x * d0.x + s0.y * d0.y + s1.x * d1.x + s1.y * d1.y;
        t += __shfl_xor_sync(mask, t, 8);
        t += __shfl_xor_sync(mask, t, 4);
        t += __shfl_xor_sync(mask, t, 2);
        t += __shfl_xor_sync(mask, t, 1);

        const float p = __expf(t >= 0.f ? t : 0.2f * t);   // leaky_relu(0.2)
        if (li == 0) zloc += p;

        float* dp = out + (size_t)dst * D + li * 4;
        asm volatile("red.global.add.v4.f32 [%0], {%1,%2,%3,%4};"
                     :: "l"(dp), "f"(p * s0.x), "f"(p * s0.y),
                        "f"(p * s1.x), "f"(p * s1.y)
                     : "memory");
    }

    float z = zloc;
    #pragma unroll
    for (int o = 16; o > 0; o >>= 1) z += __shfl_xor_sync(0xffffffffu, z, o);
    __shared__ float sz[8];
    if (lane == 0) sz[threadIdx.x >> 5] = z;
    __syncthreads();
    if (threadIdx.x == 0) {
        float s = 0.f;
        #pragma unroll
        for (int w = 0; w < 8; w++) s += sz[w];
        atomicAdd(&g_Z, s);
    }
}

// ---------------------------------------------------------------------------
// finalize: out = relu(out) / Z. ldcs/stcs: read-once (L2-warm), write-once.
// ---------------------------------------------------------------------------
__global__ void __launch_bounds__(256) finalize_kernel(float* __restrict__ out, int n)
{
    const float invZ = 1.0f / g_Z;
    const int n4 = n >> 2;
    float4* o4 = (float4*)out;
    const int st = gridDim.x * blockDim.x;
    for (int i = blockIdx.x * blockDim.x + threadIdx.x; i < n4; i += st) {
        float4 v = __ldcs(o4 + i);
        v.x = v.x > 0.f ? v.x * invZ : 0.f;
        v.y = v.y > 0.f ? v.y * invZ : 0.f;
        v.z = v.z > 0.f ? v.z * invZ : 0.f;
        v.w = v.w > 0.f ? v.w * invZ : 0.f;
        __stcs(o4 + i, v);
    }
}

// ---------------------------------------------------------------------------
// Launch: memset(out) on side stream ∥ build_y (also zeroes Z); join; edge;
// finalize.
// ---------------------------------------------------------------------------
extern "C" void kernel_launch(void* const* d_in, const int* in_sizes, int n_in,
                              void* d_out, int out_size)
{
    const int*   uidx = (const int*)d_in[0];
    const int*   iidx = (const int*)d_in[1];
    const int*   ei   = (const int*)d_in[2];
    const float* ut   = (const float*)d_in[5];
    const float* et   = (const float*)d_in[6];
    const float* W    = (const float*)d_in[7];
    float* out = (float*)d_out;
    const int E = in_sizes[2] / 2;

    static cudaStream_t s2 = nullptr;
    static cudaEvent_t ev_fork = nullptr, ev_join = nullptr;
    if (s2 == nullptr) {
        cudaStreamCreateWithFlags(&s2, cudaStreamNonBlocking);
        cudaEventCreateWithFlags(&ev_fork, cudaEventDisableTiming);
        cudaEventCreateWithFlags(&ev_join, cudaEventDisableTiming);
    }

    cudaEventRecord(ev_fork, 0);
    cudaStreamWaitEvent(s2, ev_fork, 0);
    cudaMemsetAsync(out, 0, (size_t)out_size * sizeof(float), s2);
    cudaEventRecord(ev_join, s2);

    build_y_kernel<<<296, 256>>>(uidx, iidx, ut, et, W);

    cudaStreamWaitEvent(0, ev_join, 0);
    edge_kernel<<<1184, 256>>>(ei, E, out);
    finalize_kernel<<<1184, 256>>>(out, out_size);
}